// round 16
// baseline (speedup 1.0000x reference)
#include <cuda_runtime.h>
#include <math.h>
#include <stdint.h>

#define DEV_EPS 0.025f

// ---------------- device scratch ----------------
__device__ float g_Wd[4096 * 128];       // dup'd weights: [k][128] = (w,w) pairs, quad-interleaved
__device__ float g_part[8 * 4096 * 64];  // k-split GEMM partials [kz][patch][ch]
__device__ float g_pt[16 * 4096];        // tconv partials [kz*2+h][patch]
__device__ float g_s[4096];              // channel-summed metric per patch
__device__ float g_tt[4096];             // DEV_EPS + t per patch
__device__ float g_scale1[64];
__device__ float g_shift1[64];
__device__ float g_w2[64];
__device__ float g_misc[4];              // [0]=b2 [1]=scale_t [2]=shift_t

__device__ __forceinline__ float ex2a(float x) {
    float y; asm("ex2.approx.ftz.f32 %0, %1;" : "=f"(y) : "f"(x)); return y;
}
__device__ __forceinline__ float lg2a(float x) {
    float y; asm("lg2.approx.f32 %0, %1;" : "=f"(y) : "f"(x)); return y;
}
__device__ __forceinline__ void cpa16(uint32_t dst, const void* src) {
    asm volatile("cp.async.cg.shared.global [%0], [%1], 16;" :: "r"(dst), "l"(src));
}

// ---------------- prep: duplicate+interleave conv1 weights ----------------
__global__ void prep_wd_kernel(const float* __restrict__ conv1_w) {
    int idx = blockIdx.x * blockDim.x + threadIdx.x;  // 524288
    int k = idx >> 7, f = idx & 127;
    int q = f >> 5, cg = (f >> 2) & 7, e = f & 3;
    int ch = 8 * cg + 2 * q + (e >> 1);
    g_Wd[idx] = conv1_w[ch * 4096 + k];
}

// ---------------- prep: BN folding + conv2 channel-sum ----------------
__global__ void prep_small_kernel(const float* __restrict__ conv1_b,
                                  const float* __restrict__ bn1_g,
                                  const float* __restrict__ bn1_b,
                                  const float* __restrict__ bn1_m,
                                  const float* __restrict__ bn1_v,
                                  const float* __restrict__ conv2_w,
                                  const float* __restrict__ conv2_b,
                                  const float* __restrict__ tconv_b,
                                  const float* __restrict__ bnt_g,
                                  const float* __restrict__ bnt_b,
                                  const float* __restrict__ bnt_m,
                                  const float* __restrict__ bnt_v) {
    int ch = threadIdx.x;
    if (ch < 64) {
        float inv = 1.0f / sqrtf(bn1_v[ch] + 1e-5f);
        float sc = bn1_g[ch] * inv;
        g_scale1[ch] = sc;
        g_shift1[ch] = sc * (conv1_b[ch] - bn1_m[ch]) + bn1_b[ch];
        float w2 = 0.f;
        for (int cl = 0; cl < 64; ++cl) w2 += conv2_w[cl * 64 + ch];
        g_w2[ch] = w2;
    }
    if (ch == 0) {
        float b2 = 0.f;
        for (int cl = 0; cl < 64; ++cl) b2 += conv2_b[cl];
        g_misc[0] = b2;
        float it = 1.0f / sqrtf(bnt_v[0] + 1e-5f);
        float st = bnt_g[0] * it;
        g_misc[1] = st;
        g_misc[2] = st * (tconv_b[0] - bnt_m[0]) + bnt_b[0];
    }
}

// ---------------- patch GEMM + fused temperature head ----------------
// Grid (32 mtiles, 8 kz), 256 threads, 2 CTAs/SM (16 warps/SM).
// K slice 512 = 32 chunks of 16 k. Threads h=0/1 compute the SAME 8p x 8ch
// micro-tile over complementary k-halves; inner loop = 32 FFMA2 + 6 LDS.128.
// ONE sync per chunk (program order covers the buffer hazard).
#define ATILE (16 * 128)
#define WTILE (16 * 128)
#define TWOFF (2 * ATILE + 2 * WTILE)
#define DYN_SMEM ((TWOFF + 512) * 4)  // 34816 B

extern __shared__ float smg[];

__global__ __launch_bounds__(256, 2) void gemm_kernel(const float* __restrict__ x,
                                                      const float* __restrict__ tw) {
    const int tid = threadIdx.x;
    const int t7 = tid & 127, h = tid >> 7;  // h = k-half within chunk
    const int mtile = blockIdx.x, kz = blockIdx.y;
    const int pg = t7 >> 3;  // 0..15 -> patches pg*8..+7
    const int cg = t7 & 7;   // 0..7  -> channels cg*8..+7

    const int p = (mtile << 7) + t7;
    const int b = p >> 10, py = (p >> 5) & 31, px = p & 31;
    const float* xp = x + ((size_t)b << 22) + (py << 11) + (px << 3);

    float* As = smg;
    float* Ws = smg + 2 * ATILE;
    float* tws = smg + TWOFF;
    uint32_t wsb, twb;
    asm("{ .reg .u64 t; cvta.to.shared.u64 t, %1; cvt.u32.u64 %0, t; }"
        : "=r"(wsb) : "l"(Ws));
    asm("{ .reg .u64 t; cvta.to.shared.u64 t, %1; cvt.u32.u64 %0, t; }"
        : "=r"(twb) : "l"(tws));

    unsigned long long acc[4][8];
#pragma unroll
    for (int q = 0; q < 4; ++q)
#pragma unroll
        for (int j = 0; j < 8; ++j) acc[q][j] = 0ull;
    float tacc = 0.f;

    float4 pa[2];
    int koff = kz << 9;  // 512 k per slice

#define LDA(KO)                                                                   \
    {                                                                             \
        const int _ko = (KO);                                                     \
        const float* xc = xp + ((_ko >> 6) << 16) + ((((_ko >> 3) & 7) + h) << 8);\
        pa[0] = __ldcs((const float4*)xc);                                        \
        pa[1] = __ldcs((const float4*)(xc + 4));                                  \
    }
#define LDW(KO, BUF)                                                              \
    {                                                                             \
        const float* wg = g_Wd + (size_t)(KO) * 128;                              \
        const uint32_t wd = wsb + (uint32_t)(BUF) * (WTILE * 4);                  \
        cpa16(wd + (uint32_t)tid * 16u, wg + tid * 4);                            \
        cpa16(wd + (uint32_t)(tid + 256) * 16u, wg + (tid + 256) * 4);            \
        asm volatile("cp.async.commit_group;");                                   \
    }

    LDA(koff);
    // tw slice (512 floats) FIRST so it joins LDW's group 0.
    if (tid < 128) cpa16(twb + (uint32_t)tid * 16u, tw + (kz << 9) + tid * 4);
    LDW(koff, 0);

    for (int cc = 0; cc < 32; ++cc) {
        float* A = As + (cc & 1) * ATILE;
        float* W = Ws + (cc & 1) * WTILE;
#pragma unroll
        for (int e = 0; e < 4; ++e) {
            A[(h * 8 + 2 * e + 0) * 128 + t7] = (&pa[e >> 1].x)[(e & 1) * 2 + 0];
            A[(h * 8 + 2 * e + 1) * 128 + t7] = (&pa[e >> 1].x)[(e & 1) * 2 + 1];
        }
        asm volatile("cp.async.wait_group 0;");
        __syncthreads();

        // fused temperature dot (this thread's k-half of the chunk)
        {
            const float* twc = tws + (cc << 4) + (h << 3);
            tacc = fmaf(pa[0].x, twc[0], tacc);
            tacc = fmaf(pa[0].y, twc[1], tacc);
            tacc = fmaf(pa[0].z, twc[2], tacc);
            tacc = fmaf(pa[0].w, twc[3], tacc);
            tacc = fmaf(pa[1].x, twc[4], tacc);
            tacc = fmaf(pa[1].y, twc[5], tacc);
            tacc = fmaf(pa[1].z, twc[6], tacc);
            tacc = fmaf(pa[1].w, twc[7], tacc);
        }

        if (cc < 31) {
            LDA(koff + 16);
            LDW(koff + 16, (cc + 1) & 1);
        }
        koff += 16;

#pragma unroll 8
        for (int kk = 0; kk < 8; ++kk) {
            const int k = (h << 3) + kk;
            const float* ar = &A[(k << 7) + (pg << 3)];
            ulonglong2 a01 = *(const ulonglong2*)ar;
            ulonglong2 a23 = *(const ulonglong2*)(ar + 4);
            const float* wr = &W[(k << 7) + (cg << 2)];
            ulonglong2 wq0 = *(const ulonglong2*)wr;
            ulonglong2 wq1 = *(const ulonglong2*)(wr + 32);
            ulonglong2 wq2 = *(const ulonglong2*)(wr + 64);
            ulonglong2 wq3 = *(const ulonglong2*)(wr + 96);
            unsigned long long aq[4] = {a01.x, a01.y, a23.x, a23.y};
            unsigned long long wp[8] = {wq0.x, wq0.y, wq1.x, wq1.y,
                                        wq2.x, wq2.y, wq3.x, wq3.y};
#pragma unroll
            for (int q = 0; q < 4; ++q)
#pragma unroll
                for (int j = 0; j < 8; ++j)
                    asm("fma.rn.f32x2 %0, %1, %2, %0;"
                        : "+l"(acc[q][j]) : "l"(aq[q]), "l"(wp[j]));
        }
        // no trailing sync: top-of-loop sync + program order cover the hazard
    }

    // all compute must finish before staging overwrites the A region
    __syncthreads();

    // ---- combine h=1 partials into h=0 via smem staging ----
    {
        unsigned long long* stg = (unsigned long long*)smg;  // 4096 u64 = 32KB
        if (h == 1) {
#pragma unroll
            for (int q = 0; q < 4; ++q)
#pragma unroll
                for (int j = 0; j < 8; ++j)
                    stg[(q * 8 + j) * 128 + t7] = acc[q][j];
        }
        __syncthreads();
        if (h == 0) {
#pragma unroll
            for (int q = 0; q < 4; ++q)
#pragma unroll
                for (int j = 0; j < 8; ++j) {
                    unsigned long long o = stg[(q * 8 + j) * 128 + t7];
                    asm("add.rn.f32x2 %0, %0, %1;" : "+l"(acc[q][j]) : "l"(o));
                }
        }
    }

    if (h == 0) {
#pragma unroll
        for (int q = 0; q < 4; ++q) {
            int p0 = (mtile << 7) + (pg << 3) + 2 * q;
            float* d0 = g_part + ((size_t)kz * 4096 + p0) * 64 + (cg << 3);
            float* d1 = d0 + 64;
            float4 lo0, lo1, hi0, hi1;
            lo0.x = __uint_as_float((uint32_t)acc[q][0]);
            lo0.y = __uint_as_float((uint32_t)acc[q][1]);
            lo0.z = __uint_as_float((uint32_t)acc[q][2]);
            lo0.w = __uint_as_float((uint32_t)acc[q][3]);
            lo1.x = __uint_as_float((uint32_t)acc[q][4]);
            lo1.y = __uint_as_float((uint32_t)acc[q][5]);
            lo1.z = __uint_as_float((uint32_t)acc[q][6]);
            lo1.w = __uint_as_float((uint32_t)acc[q][7]);
            hi0.x = __uint_as_float((uint32_t)(acc[q][0] >> 32));
            hi0.y = __uint_as_float((uint32_t)(acc[q][1] >> 32));
            hi0.z = __uint_as_float((uint32_t)(acc[q][2] >> 32));
            hi0.w = __uint_as_float((uint32_t)(acc[q][3] >> 32));
            hi1.x = __uint_as_float((uint32_t)(acc[q][4] >> 32));
            hi1.y = __uint_as_float((uint32_t)(acc[q][5] >> 32));
            hi1.z = __uint_as_float((uint32_t)(acc[q][6] >> 32));
            hi1.w = __uint_as_float((uint32_t)(acc[q][7] >> 32));
            *(float4*)d0 = lo0;
            *(float4*)(d0 + 4) = lo1;
            *(float4*)d1 = hi0;
            *(float4*)(d1 + 4) = hi1;
        }
    }
    g_pt[(kz * 2 + h) * 4096 + p] = tacc;
}

// ---------------- epilogue: warp-per-patch over 8 kz slices ----------------
__global__ __launch_bounds__(256) void epi_kernel() {
    const int warp = threadIdx.x >> 5, lane = threadIdx.x & 31;
    const int hh = lane >> 4, l = lane & 15;
    const int p = blockIdx.x * 8 + warp;
    const int c = l << 2;

    float4 y = {0.f, 0.f, 0.f, 0.f};
#pragma unroll
    for (int i = 0; i < 4; ++i) {
        int kz = hh * 4 + i;
        float4 v = *(const float4*)(g_part + ((size_t)kz * 4096 + p) * 64 + c);
        y.x += v.x; y.y += v.y; y.z += v.z; y.w += v.w;
    }
    y.x += __shfl_xor_sync(0xffffffffu, y.x, 16);
    y.y += __shfl_xor_sync(0xffffffffu, y.y, 16);
    y.z += __shfl_xor_sync(0xffffffffu, y.z, 16);
    y.w += __shfl_xor_sync(0xffffffffu, y.w, 16);

    float v = fmaxf(fmaf(g_scale1[c + 0], y.x, g_shift1[c + 0]), 0.f) * g_w2[c + 0] +
              fmaxf(fmaf(g_scale1[c + 1], y.y, g_shift1[c + 1]), 0.f) * g_w2[c + 1] +
              fmaxf(fmaf(g_scale1[c + 2], y.z, g_shift1[c + 2]), 0.f) * g_w2[c + 2] +
              fmaxf(fmaf(g_scale1[c + 3], y.w, g_shift1[c + 3]), 0.f) * g_w2[c + 3];
    float tv = (lane < 16) ? g_pt[lane * 4096 + p] : 0.f;
    tv += __shfl_xor_sync(0xffffffffu, tv, 16);
#pragma unroll
    for (int o = 8; o; o >>= 1) {
        v += __shfl_xor_sync(0xffffffffu, v, o);
        tv += __shfl_xor_sync(0xffffffffu, tv, o);
    }
    if (lane == 0) {
        g_s[p] = v + g_misc[0];
        float t = fmaxf(fmaf(g_misc[1], tv, g_misc[2]), 0.f);
        g_tt[p] = DEV_EPS + t;
    }
}

// ---------------- softmax: warp-per-row, register logits, MUFU fast path ----------------
// Per-iter max retained (stale max underflows all exps on one-hot rows -> NaN).
// Plain stores (not __stcs): 67MB output fits L2; kernel completes at L2 write
// speed, dirty writeback deferred into the next replay's compute phase.
__global__ __launch_bounds__(256) void softmax_kernel(float* __restrict__ out) {
    const int w = threadIdx.x >> 5, lane = threadIdx.x & 31;
    const int r = blockIdx.x * 8 + w;
    const int b = r >> 10, i = r & 1023;
    const float si = g_s[r];
    const float invt = 1.0f / g_tt[r];
    const float c = invt * 1.4426950408889634f;

    float l2[32];
#pragma unroll
    for (int q = 0; q < 8; ++q) {
        int j = (q << 7) + (lane << 2);
        float4 s4 = *(const float4*)(g_s + (b << 10) + j);
        float sv[4] = {s4.x, s4.y, s4.z, s4.w};
#pragma unroll
        for (int u = 0; u < 4; ++u) {
            float d = si - sv[u];
            float val = -d * d;
            if (j + u == i) val -= 1000.0f;
            l2[q * 4 + u] = val * c;
        }
    }

    float mloc = l2[0];
#pragma unroll
    for (int q = 1; q < 32; ++q) mloc = fmaxf(mloc, l2[q]);

    const size_t rbase = ((size_t)b << 20) + ((size_t)i << 10);
#pragma unroll 1
    for (int it = 0; it < 4; ++it) {
        float m = mloc;
#pragma unroll
        for (int o = 16; o; o >>= 1) m = fmaxf(m, __shfl_xor_sync(0xffffffffu, m, o));
        float e[32];
        float s = 0.f;
#pragma unroll
        for (int q = 0; q < 32; ++q) {
            e[q] = ex2a(l2[q] - m);
            s += e[q];
        }
#pragma unroll
        for (int o = 16; o; o >>= 1) s += __shfl_xor_sync(0xffffffffu, s, o);
        float invS = 1.0f / s;
#pragma unroll
        for (int q = 0; q < 32; ++q) e[q] *= invS;  // e[] now holds p[]
        float* op = out + (((size_t)it) << 22) + rbase + (lane << 2);
#pragma unroll
        for (int q = 0; q < 8; ++q) {
            float4 po;
            po.x = e[q * 4 + 0];
            po.y = e[q * 4 + 1];
            po.z = e[q * 4 + 2];
            po.w = e[q * 4 + 3];
            *(float4*)(op + (q << 7)) = po;
        }
        if (it < 3) {
            float mn = -3.4e38f;
#pragma unroll
            for (int q = 0; q < 32; ++q) {
                float om = fmaxf(1.0f - e[q], 1e-38f);
                l2[q] += lg2a(om) * invt;
                mn = fmaxf(mn, l2[q]);
            }
            mloc = mn;
        }
    }
}

// ---------------- launch ----------------
extern "C" void kernel_launch(void* const* d_in, const int* in_sizes, int n_in,
                              void* d_out, int out_size) {
    const float* x = (const float*)d_in[0];
    const float* conv1_w = (const float*)d_in[1];
    const float* conv1_b = (const float*)d_in[2];
    const float* bn1_g = (const float*)d_in[3];
    const float* bn1_b = (const float*)d_in[4];
    const float* bn1_m = (const float*)d_in[5];
    const float* bn1_v = (const float*)d_in[6];
    const float* conv2_w = (const float*)d_in[7];
    const float* conv2_b = (const float*)d_in[8];
    const float* tconv_w = (const float*)d_in[9];
    const float* tconv_b = (const float*)d_in[10];
    const float* bnt_g = (const float*)d_in[11];
    const float* bnt_b = (const float*)d_in[12];
    const float* bnt_m = (const float*)d_in[13];
    const float* bnt_v = (const float*)d_in[14];
    float* out = (float*)d_out;

    static int smem_set = 0;
    if (!smem_set) {
        cudaFuncSetAttribute(gemm_kernel,
                             cudaFuncAttributeMaxDynamicSharedMemorySize, DYN_SMEM);
        smem_set = 1;
    }

    prep_wd_kernel<<<2048, 256>>>(conv1_w);
    prep_small_kernel<<<1, 64>>>(conv1_b, bn1_g, bn1_b, bn1_m, bn1_v,
                                 conv2_w, conv2_b, tconv_b, bnt_g, bnt_b, bnt_m, bnt_v);
    dim3 g(32, 8);
    gemm_kernel<<<g, 256, DYN_SMEM>>>(x, tconv_w);
    epi_kernel<<<512, 256>>>();
    softmax_kernel<<<512, 256>>>(out);
}

// round 17
// speedup vs baseline: 1.0758x; 1.0758x over previous
#include <cuda_runtime.h>
#include <math.h>
#include <stdint.h>

#define DEV_EPS 0.025f

// ---------------- device scratch ----------------
__device__ float g_Wd[4096 * 128];       // dup'd weights: [k][128] = (w,w) pairs, quad-interleaved
__device__ float g_part[8 * 4096 * 64];  // k-split GEMM partials [kz][patch][ch]
__device__ float g_pt[16 * 4096];        // tconv partials [kz*2+h][patch]
__device__ float g_s[4096];              // channel-summed metric per patch
__device__ float g_tt[4096];             // DEV_EPS + t per patch
__device__ float g_scale1[64];
__device__ float g_shift1[64];
__device__ float g_w2[64];
__device__ float g_misc[4];              // [0]=b2 [1]=scale_t [2]=shift_t

__device__ __forceinline__ float ex2a(float x) {
    float y; asm("ex2.approx.ftz.f32 %0, %1;" : "=f"(y) : "f"(x)); return y;
}
__device__ __forceinline__ float lg2a(float x) {
    float y; asm("lg2.approx.f32 %0, %1;" : "=f"(y) : "f"(x)); return y;
}
__device__ __forceinline__ void cpa16(uint32_t dst, const void* src) {
    asm volatile("cp.async.cg.shared.global [%0], [%1], 16;" :: "r"(dst), "l"(src));
}

// ---------------- prep: duplicate+interleave conv1 weights ----------------
__global__ void prep_wd_kernel(const float* __restrict__ conv1_w) {
    int idx = blockIdx.x * blockDim.x + threadIdx.x;  // 524288
    int k = idx >> 7, f = idx & 127;
    int q = f >> 5, cg = (f >> 2) & 7, e = f & 3;
    int ch = 8 * cg + 2 * q + (e >> 1);
    g_Wd[idx] = conv1_w[ch * 4096 + k];
}

// ---------------- prep: BN folding + conv2 channel-sum ----------------
__global__ void prep_small_kernel(const float* __restrict__ conv1_b,
                                  const float* __restrict__ bn1_g,
                                  const float* __restrict__ bn1_b,
                                  const float* __restrict__ bn1_m,
                                  const float* __restrict__ bn1_v,
                                  const float* __restrict__ conv2_w,
                                  const float* __restrict__ conv2_b,
                                  const float* __restrict__ tconv_b,
                                  const float* __restrict__ bnt_g,
                                  const float* __restrict__ bnt_b,
                                  const float* __restrict__ bnt_m,
                                  const float* __restrict__ bnt_v) {
    int ch = threadIdx.x;
    if (ch < 64) {
        float inv = 1.0f / sqrtf(bn1_v[ch] + 1e-5f);
        float sc = bn1_g[ch] * inv;
        g_scale1[ch] = sc;
        g_shift1[ch] = sc * (conv1_b[ch] - bn1_m[ch]) + bn1_b[ch];
        float w2 = 0.f;
        for (int cl = 0; cl < 64; ++cl) w2 += conv2_w[cl * 64 + ch];
        g_w2[ch] = w2;
    }
    if (ch == 0) {
        float b2 = 0.f;
        for (int cl = 0; cl < 64; ++cl) b2 += conv2_b[cl];
        g_misc[0] = b2;
        float it = 1.0f / sqrtf(bnt_v[0] + 1e-5f);
        float st = bnt_g[0] * it;
        g_misc[1] = st;
        g_misc[2] = st * (tconv_b[0] - bnt_m[0]) + bnt_b[0];
    }
}

// ---------------- patch GEMM + fused temperature head (SCALAR FFMA) ----------------
// Grid (32 mtiles, 8 kz), 256 threads, 2 CTAs/SM.
// Identical pipeline to R16; inner loop is 64 scalar FFMA per k (A/B vs f32x2:
// tests whether scalar FFMA runs 128 lanes/cyc/SM vs FFMA2's measured 64).
// W dup'd layout reused: take .x/.z of each (w,w) pair -> no prep change.
#define ATILE (16 * 128)
#define WTILE (16 * 128)
#define TWOFF (2 * ATILE + 2 * WTILE)
#define DYN_SMEM ((TWOFF + 512) * 4)  // 34816 B

extern __shared__ float smg[];

__global__ __launch_bounds__(256, 2) void gemm_kernel(const float* __restrict__ x,
                                                      const float* __restrict__ tw) {
    const int tid = threadIdx.x;
    const int t7 = tid & 127, h = tid >> 7;  // h = k-half within chunk
    const int mtile = blockIdx.x, kz = blockIdx.y;
    const int pg = t7 >> 3;  // 0..15 -> patches pg*8..+7
    const int cg = t7 & 7;   // 0..7  -> channels cg*8..+7

    const int p = (mtile << 7) + t7;
    const int b = p >> 10, py = (p >> 5) & 31, px = p & 31;
    const float* xp = x + ((size_t)b << 22) + (py << 11) + (px << 3);

    float* As = smg;
    float* Ws = smg + 2 * ATILE;
    float* tws = smg + TWOFF;
    uint32_t wsb, twb;
    asm("{ .reg .u64 t; cvta.to.shared.u64 t, %1; cvt.u32.u64 %0, t; }"
        : "=r"(wsb) : "l"(Ws));
    asm("{ .reg .u64 t; cvta.to.shared.u64 t, %1; cvt.u32.u64 %0, t; }"
        : "=r"(twb) : "l"(tws));

    float acc[8][8];
#pragma unroll
    for (int i = 0; i < 8; ++i)
#pragma unroll
        for (int j = 0; j < 8; ++j) acc[i][j] = 0.f;
    float tacc = 0.f;

    float4 pa[2];
    int koff = kz << 9;  // 512 k per slice

#define LDA(KO)                                                                   \
    {                                                                             \
        const int _ko = (KO);                                                     \
        const float* xc = xp + ((_ko >> 6) << 16) + ((((_ko >> 3) & 7) + h) << 8);\
        pa[0] = __ldcs((const float4*)xc);                                        \
        pa[1] = __ldcs((const float4*)(xc + 4));                                  \
    }
#define LDW(KO, BUF)                                                              \
    {                                                                             \
        const float* wg = g_Wd + (size_t)(KO) * 128;                              \
        const uint32_t wd = wsb + (uint32_t)(BUF) * (WTILE * 4);                  \
        cpa16(wd + (uint32_t)tid * 16u, wg + tid * 4);                            \
        cpa16(wd + (uint32_t)(tid + 256) * 16u, wg + (tid + 256) * 4);            \
        asm volatile("cp.async.commit_group;");                                   \
    }

    LDA(koff);
    // tw slice (512 floats) FIRST so it joins LDW's group 0.
    if (tid < 128) cpa16(twb + (uint32_t)tid * 16u, tw + (kz << 9) + tid * 4);
    LDW(koff, 0);

    for (int cc = 0; cc < 32; ++cc) {
        float* A = As + (cc & 1) * ATILE;
        float* W = Ws + (cc & 1) * WTILE;
#pragma unroll
        for (int e = 0; e < 4; ++e) {
            A[(h * 8 + 2 * e + 0) * 128 + t7] = (&pa[e >> 1].x)[(e & 1) * 2 + 0];
            A[(h * 8 + 2 * e + 1) * 128 + t7] = (&pa[e >> 1].x)[(e & 1) * 2 + 1];
        }
        asm volatile("cp.async.wait_group 0;");
        __syncthreads();

        // fused temperature dot (this thread's k-half of the chunk)
        {
            const float* twc = tws + (cc << 4) + (h << 3);
            tacc = fmaf(pa[0].x, twc[0], tacc);
            tacc = fmaf(pa[0].y, twc[1], tacc);
            tacc = fmaf(pa[0].z, twc[2], tacc);
            tacc = fmaf(pa[0].w, twc[3], tacc);
            tacc = fmaf(pa[1].x, twc[4], tacc);
            tacc = fmaf(pa[1].y, twc[5], tacc);
            tacc = fmaf(pa[1].z, twc[6], tacc);
            tacc = fmaf(pa[1].w, twc[7], tacc);
        }

        if (cc < 31) {
            LDA(koff + 16);
            LDW(koff + 16, (cc + 1) & 1);
        }
        koff += 16;

#pragma unroll 8
        for (int kk = 0; kk < 8; ++kk) {
            const int k = (h << 3) + kk;
            const float* ar = &A[(k << 7) + (pg << 3)];
            float4 a0 = *(const float4*)ar;
            float4 a1 = *(const float4*)(ar + 4);
            const float* wr = &W[(k << 7) + (cg << 2)];
            float4 w0 = *(const float4*)wr;         // (w0,w0,w1,w1)
            float4 w1 = *(const float4*)(wr + 32);  // (w2,w2,w3,w3)
            float4 w2 = *(const float4*)(wr + 64);  // (w4,w4,w5,w5)
            float4 w3 = *(const float4*)(wr + 96);  // (w6,w6,w7,w7)
            float a[8] = {a0.x, a0.y, a0.z, a0.w, a1.x, a1.y, a1.z, a1.w};
            float w[8] = {w0.x, w0.z, w1.x, w1.z, w2.x, w2.z, w3.x, w3.z};
#pragma unroll
            for (int i = 0; i < 8; ++i)
#pragma unroll
                for (int j = 0; j < 8; ++j)
                    acc[i][j] = fmaf(a[i], w[j], acc[i][j]);
        }
        // no trailing sync: top-of-loop sync + program order cover the hazard
    }

    // all compute must finish before staging overwrites the A region
    __syncthreads();

    // ---- combine h=1 partials into h=0 via smem staging (floats) ----
    {
        float* stg = smg;  // 64 x 128 floats = 32KB
        if (h == 1) {
#pragma unroll
            for (int i = 0; i < 8; ++i)
#pragma unroll
                for (int j = 0; j < 8; ++j)
                    stg[(i * 8 + j) * 128 + t7] = acc[i][j];
        }
        __syncthreads();
        if (h == 0) {
#pragma unroll
            for (int i = 0; i < 8; ++i)
#pragma unroll
                for (int j = 0; j < 8; ++j)
                    acc[i][j] += stg[(i * 8 + j) * 128 + t7];
        }
    }

    if (h == 0) {
#pragma unroll
        for (int i = 0; i < 8; ++i) {
            int p0 = (mtile << 7) + (pg << 3) + i;
            float* d = g_part + ((size_t)kz * 4096 + p0) * 64 + (cg << 3);
            float4 o0, o1;
            o0.x = acc[i][0]; o0.y = acc[i][1]; o0.z = acc[i][2]; o0.w = acc[i][3];
            o1.x = acc[i][4]; o1.y = acc[i][5]; o1.z = acc[i][6]; o1.w = acc[i][7];
            *(float4*)d = o0;
            *(float4*)(d + 4) = o1;
        }
    }
    g_pt[(kz * 2 + h) * 4096 + p] = tacc;
}

// ---------------- epilogue: warp-per-patch over 8 kz slices ----------------
__global__ __launch_bounds__(256) void epi_kernel() {
    const int warp = threadIdx.x >> 5, lane = threadIdx.x & 31;
    const int hh = lane >> 4, l = lane & 15;
    const int p = blockIdx.x * 8 + warp;
    const int c = l << 2;

    float4 y = {0.f, 0.f, 0.f, 0.f};
#pragma unroll
    for (int i = 0; i < 4; ++i) {
        int kz = hh * 4 + i;
        float4 v = *(const float4*)(g_part + ((size_t)kz * 4096 + p) * 64 + c);
        y.x += v.x; y.y += v.y; y.z += v.z; y.w += v.w;
    }
    y.x += __shfl_xor_sync(0xffffffffu, y.x, 16);
    y.y += __shfl_xor_sync(0xffffffffu, y.y, 16);
    y.z += __shfl_xor_sync(0xffffffffu, y.z, 16);
    y.w += __shfl_xor_sync(0xffffffffu, y.w, 16);

    float v = fmaxf(fmaf(g_scale1[c + 0], y.x, g_shift1[c + 0]), 0.f) * g_w2[c + 0] +
              fmaxf(fmaf(g_scale1[c + 1], y.y, g_shift1[c + 1]), 0.f) * g_w2[c + 1] +
              fmaxf(fmaf(g_scale1[c + 2], y.z, g_shift1[c + 2]), 0.f) * g_w2[c + 2] +
              fmaxf(fmaf(g_scale1[c + 3], y.w, g_shift1[c + 3]), 0.f) * g_w2[c + 3];
    float tv = (lane < 16) ? g_pt[lane * 4096 + p] : 0.f;
    tv += __shfl_xor_sync(0xffffffffu, tv, 16);
#pragma unroll
    for (int o = 8; o; o >>= 1) {
        v += __shfl_xor_sync(0xffffffffu, v, o);
        tv += __shfl_xor_sync(0xffffffffu, tv, o);
    }
    if (lane == 0) {
        g_s[p] = v + g_misc[0];
        float t = fmaxf(fmaf(g_misc[1], tv, g_misc[2]), 0.f);
        g_tt[p] = DEV_EPS + t;
    }
}

// ---------------- softmax: warp-per-row, register logits, MUFU fast path ----------------
// Per-iter max retained (stale max underflows all exps on one-hot rows -> NaN).
__global__ __launch_bounds__(256) void softmax_kernel(float* __restrict__ out) {
    const int w = threadIdx.x >> 5, lane = threadIdx.x & 31;
    const int r = blockIdx.x * 8 + w;
    const int b = r >> 10, i = r & 1023;
    const float si = g_s[r];
    const float invt = 1.0f / g_tt[r];
    const float c = invt * 1.4426950408889634f;

    float l2[32];
#pragma unroll
    for (int q = 0; q < 8; ++q) {
        int j = (q << 7) + (lane << 2);
        float4 s4 = *(const float4*)(g_s + (b << 10) + j);
        float sv[4] = {s4.x, s4.y, s4.z, s4.w};
#pragma unroll
        for (int u = 0; u < 4; ++u) {
            float d = si - sv[u];
            float val = -d * d;
            if (j + u == i) val -= 1000.0f;
            l2[q * 4 + u] = val * c;
        }
    }

    float mloc = l2[0];
#pragma unroll
    for (int q = 1; q < 32; ++q) mloc = fmaxf(mloc, l2[q]);

    const size_t rbase = ((size_t)b << 20) + ((size_t)i << 10);
#pragma unroll 1
    for (int it = 0; it < 4; ++it) {
        float m = mloc;
#pragma unroll
        for (int o = 16; o; o >>= 1) m = fmaxf(m, __shfl_xor_sync(0xffffffffu, m, o));
        float e[32];
        float s = 0.f;
#pragma unroll
        for (int q = 0; q < 32; ++q) {
            e[q] = ex2a(l2[q] - m);
            s += e[q];
        }
#pragma unroll
        for (int o = 16; o; o >>= 1) s += __shfl_xor_sync(0xffffffffu, s, o);
        float invS = 1.0f / s;
#pragma unroll
        for (int q = 0; q < 32; ++q) e[q] *= invS;  // e[] now holds p[]
        float* op = out + (((size_t)it) << 22) + rbase + (lane << 2);
#pragma unroll
        for (int q = 0; q < 8; ++q) {
            float4 po;
            po.x = e[q * 4 + 0];
            po.y = e[q * 4 + 1];
            po.z = e[q * 4 + 2];
            po.w = e[q * 4 + 3];
            *(float4*)(op + (q << 7)) = po;
        }
        if (it < 3) {
            float mn = -3.4e38f;
#pragma unroll
            for (int q = 0; q < 32; ++q) {
                float om = fmaxf(1.0f - e[q], 1e-38f);
                l2[q] += lg2a(om) * invt;
                mn = fmaxf(mn, l2[q]);
            }
            mloc = mn;
        }
    }
}

// ---------------- launch ----------------
extern "C" void kernel_launch(void* const* d_in, const int* in_sizes, int n_in,
                              void* d_out, int out_size) {
    const float* x = (const float*)d_in[0];
    const float* conv1_w = (const float*)d_in[1];
    const float* conv1_b = (const float*)d_in[2];
    const float* bn1_g = (const float*)d_in[3];
    const float* bn1_b = (const float*)d_in[4];
    const float* bn1_m = (const float*)d_in[5];
    const float* bn1_v = (const float*)d_in[6];
    const float* conv2_w = (const float*)d_in[7];
    const float* conv2_b = (const float*)d_in[8];
    const float* tconv_w = (const float*)d_in[9];
    const float* tconv_b = (const float*)d_in[10];
    const float* bnt_g = (const float*)d_in[11];
    const float* bnt_b = (const float*)d_in[12];
    const float* bnt_m = (const float*)d_in[13];
    const float* bnt_v = (const float*)d_in[14];
    float* out = (float*)d_out;

    static int smem_set = 0;
    if (!smem_set) {
        cudaFuncSetAttribute(gemm_kernel,
                             cudaFuncAttributeMaxDynamicSharedMemorySize, DYN_SMEM);
        smem_set = 1;
    }

    prep_wd_kernel<<<2048, 256>>>(conv1_w);
    prep_small_kernel<<<1, 64>>>(conv1_b, bn1_g, bn1_b, bn1_m, bn1_v,
                                 conv2_w, conv2_b, tconv_b, bnt_g, bnt_b, bnt_m, bnt_v);
    dim3 g(32, 8);
    gemm_kernel<<<g, 256, DYN_SMEM>>>(x, tconv_w);
    epi_kernel<<<512, 256>>>();
    softmax_kernel<<<512, 256>>>(out);
}